// round 4
// baseline (speedup 1.0000x reference)
#include <cuda_runtime.h>

#define HW    16384      // H*W
#define ROWS  4096       // B*C
#define CC    128
#define BB    32
#define TOPK  1638       // round(16384 * 0.1)
#define HID   8
#define NT    512
#define NWARP 16
#define NB    2048       // 11-bit bins (levels 1,2)
#define NB3   1024       // 10-bit final bins
#define WCAP  384        // per-warp candidate capacity
#define CAP   (NWARP * WCAP)   // 6144 per row
#define T_LO  1.0f

__device__ float    g_avg[ROWS];
__device__ float    g_maxv[ROWS];
__device__ float    g_scale[ROWS];
__device__ unsigned g_cand[(size_t)ROWS * CAP];   // ~100 MB scratch
__device__ int      g_wlen[ROWS * NWARP];

// Order-preserving float->uint key (larger float => larger key)
__device__ __forceinline__ unsigned f2key(float f) {
    unsigned u = __float_as_uint(f);
    return u ^ ((unsigned)((int)u >> 31) | 0x80000000u);
}
__device__ __forceinline__ float key2f(unsigned k) {
    unsigned u = k ^ (((int)k < 0) ? 0x80000000u : 0xFFFFFFFFu);
    return __uint_as_float(u);
}

// Warp-aggregated histogram increment; d == -1 means skip. Full-warp only.
__device__ __forceinline__ void agg_add(int* h, int d) {
    unsigned m = __match_any_sync(0xffffffffu, d);
    if (d >= 0 && (int)(threadIdx.x & 31) == __ffs((int)m) - 1)
        atomicAdd(&h[d], __popc(m));
}

// Suffix-count select: bin b with s(b) >= rem > s(b+1), s(b)=sum_{j>=b} h[j].
template <int BPT>
__device__ __forceinline__ void suffix_select(const int* h, int rem,
                                              int* swarp, unsigned* sdigit,
                                              int* srem) {
    const int tid = threadIdx.x, lane = tid & 31, w = tid >> 5;
    const int base = tid * BPT;
    int loc[BPT];
    int tsum = 0;
#pragma unroll
    for (int i = 0; i < BPT; i++) { loc[i] = h[base + i]; tsum += loc[i]; }
    int inc = tsum;
#pragma unroll
    for (int o = 1; o < 32; o <<= 1) {
        int v = __shfl_down_sync(0xffffffffu, inc, o);
        if (lane + o < 32) inc += v;
    }
    if (lane == 0) swarp[w] = inc;
    __syncthreads();
    if (tid == 0) {
        int run = 0;
        for (int i = NWARP - 1; i >= 0; i--) { int t = swarp[i]; swarp[i] = run; run += t; }
    }
    __syncthreads();
    int s_next = (inc - tsum) + swarp[w];
#pragma unroll
    for (int i = BPT - 1; i >= 0; i--) {
        int s = loc[i] + s_next;
        if (s >= rem && s_next < rem) { *sdigit = (unsigned)(base + i); *srem = rem - s_next; }
        s_next = s;
    }
    __syncthreads();
}

// ---------------------------------------------------------------------------
// Kernel 1: streaming sweep — row max + compaction of v > T_LO to global
// ---------------------------------------------------------------------------
__global__ __launch_bounds__(NT) void topk_compact(const float* __restrict__ x) {
    __shared__ unsigned wseg_s[NWARP][WCAP];   // 24 KB
    __shared__ float fred[NWARP];

    const int tid = threadIdx.x, lane = tid & 31, w = tid >> 5;
    const int row = blockIdx.x;
    const float4* xin = (const float4*)(x + (size_t)row * HW);
    unsigned* wseg = wseg_s[w];

    int wbase = 0;
    float lmax = -3.402823466e38f;
#pragma unroll
    for (int i = 0; i < HW / (4 * NT); i++) {
        float4 v = xin[tid + i * NT];
        lmax = fmaxf(lmax, fmaxf(fmaxf(v.x, v.y), fmaxf(v.z, v.w)));
        bool h0 = v.x > T_LO, h1 = v.y > T_LO, h2 = v.z > T_LO, h3 = v.w > T_LO;
        int h = (int)h0 + (int)h1 + (int)h2 + (int)h3;
        int inc = h;                              // warp inclusive scan of h
#pragma unroll
        for (int o = 1; o < 32; o <<= 1) {
            int t = __shfl_up_sync(0xffffffffu, inc, o);
            if (lane >= o) inc += t;
        }
        int pos = wbase + inc - h;                // exclusive offset
        if (h0) { if (pos < WCAP) wseg[pos] = f2key(v.x); pos++; }
        if (h1) { if (pos < WCAP) wseg[pos] = f2key(v.y); pos++; }
        if (h2) { if (pos < WCAP) wseg[pos] = f2key(v.z); pos++; }
        if (h3) { if (pos < WCAP) wseg[pos] = f2key(v.w); pos++; }
        wbase += __shfl_sync(0xffffffffu, inc, 31);
    }
#pragma unroll
    for (int o = 16; o; o >>= 1) lmax = fmaxf(lmax, __shfl_down_sync(0xffffffffu, lmax, o));
    if (lane == 0) fred[w] = lmax;
    __syncthreads();
    if (tid == 0) {
        float m = fred[0];
        for (int i = 1; i < NWARP; i++) m = fmaxf(m, fred[i]);
        g_maxv[row] = m;
    }
    __syncwarp();
    if (lane == 0) g_wlen[row * NWARP + w] = wbase;
    const int n = min(wbase, WCAP);
    unsigned* gdst = g_cand + (size_t)row * CAP + w * WCAP;
    for (int i = lane; i < n; i += 32) gdst[i] = wseg[i];
}

// ---------------------------------------------------------------------------
// Kernel 2: exact top-k mean over the compacted candidates (register-resident)
// ---------------------------------------------------------------------------
__global__ __launch_bounds__(NT) void topk_select(const float* __restrict__ x) {
    __shared__ int      hist[NB];     // 8 KB
    __shared__ float    shist[NB3];   // 4 KB
    __shared__ int      swlen[NWARP];
    __shared__ int      swarp[NWARP];
    __shared__ unsigned sdigit;
    __shared__ int      srem, sfall;
    __shared__ float    fred[NWARP];
    __shared__ int      ired[NWARP];

    const int tid = threadIdx.x, lane = tid & 31, w = tid >> 5;
    const int row = blockIdx.x;

    if (tid < NWARP) swlen[tid] = g_wlen[row * NWARP + tid];
    __syncthreads();
    if (tid == 0) {
        int tot = 0, fb = 0;
        for (int i = 0; i < NWARP; i++) { int l = swlen[i]; if (l > WCAP) fb = 1; tot += l; }
        if (tot < TOPK) fb = 1;
        sfall = fb;
    }
    __syncthreads();

    if (!sfall) {
        // load candidates into registers (predicated — invalid slots not fetched)
        unsigned k[CAP / NT];
        const unsigned* gsrc = g_cand + (size_t)row * CAP;
#pragma unroll
        for (int i = 0; i < CAP / NT; i++) {
            int g = tid + i * NT;
            int seg = g / WCAP;
            bool valid = (g - seg * WCAP) < swlen[seg];
            k[i] = valid ? gsrc[g] : 0u;          // 0 = invalid sentinel (< any candidate)
        }

        // L1: top 11 bits
        for (int i = tid; i < NB; i += NT) hist[i] = 0;
        __syncthreads();
#pragma unroll
        for (int i = 0; i < CAP / NT; i++) agg_add(hist, k[i] ? (int)(k[i] >> 21) : -1);
        __syncthreads();
        suffix_select<NB / NT>(hist, TOPK, swarp, &sdigit, &srem);
        const unsigned d0 = sdigit; const int rem1 = srem;

        // L2: next 11 bits
        for (int i = tid; i < NB; i += NT) hist[i] = 0;
        __syncthreads();
#pragma unroll
        for (int i = 0; i < CAP / NT; i++)
            agg_add(hist, (k[i] && (k[i] >> 21) == d0) ? (int)((k[i] >> 10) & (NB - 1)) : -1);
        __syncthreads();
        suffix_select<NB / NT>(hist, rem1, swarp, &sdigit, &srem);
        const unsigned P1 = (d0 << 11) | sdigit; const int rem2 = srem;

        // L3: final 10 bits — count + value-sum histograms on sparse hits
        for (int i = tid; i < NB3; i += NT) { hist[i] = 0; shist[i] = 0.f; }
        __syncthreads();
        float lsum = 0.f;
#pragma unroll
        for (int i = 0; i < CAP / NT; i++) {
            unsigned kk = k[i];
            if (kk) {
                unsigned t = kk >> 10;
                if (t > P1) lsum += key2f(kk);
                else if (t == P1) {
                    atomicAdd(&hist[kk & (NB3 - 1)], 1);
                    atomicAdd(&shist[kk & (NB3 - 1)], key2f(kk));
                }
            }
        }
        __syncthreads();
        suffix_select<NB3 / NT>(hist, rem2, swarp, &sdigit, &srem);
        const unsigned d2 = sdigit; const int ties = srem;

        float sa = 0.f;
        for (int b = tid; b < NB3; b += NT)
            if (b > (int)d2) sa += shist[b];
        float acc = lsum + sa;
#pragma unroll
        for (int o = 16; o; o >>= 1) acc += __shfl_down_sync(0xffffffffu, acc, o);
        if (lane == 0) fred[w] = acc;
        __syncthreads();
        if (tid == 0) {
            float s = 0.f;
            for (int i = 0; i < NWARP; i++) s += fred[i];
            unsigned T = (P1 << 10) | d2;
            g_avg[row] = (s + key2f(T) * (float)ties) / (float)TOPK;
        }
    } else {
        // exact fallback: bitwise binary search for the k-th largest key
        const float4* xin = (const float4*)(x + (size_t)row * HW);
        unsigned T = 0u;
        for (int bit = 31; bit >= 0; --bit) {
            const unsigned cT = T | (1u << bit);
            int c = 0;
#pragma unroll
            for (int i = 0; i < HW / (4 * NT); i++) {
                float4 v = xin[tid + i * NT];
                c += (f2key(v.x) >= cT) + (f2key(v.y) >= cT)
                   + (f2key(v.z) >= cT) + (f2key(v.w) >= cT);
            }
#pragma unroll
            for (int o = 16; o; o >>= 1) c += __shfl_down_sync(0xffffffffu, c, o);
            if (lane == 0) ired[w] = c;
            __syncthreads();
            if (tid == 0) {
                int s = 0;
                for (int i = 0; i < NWARP; i++) s += ired[i];
                srem = s;
            }
            __syncthreads();
            if (srem >= TOPK) T = cT;
            __syncthreads();
        }
        float ls = 0.f; int lc = 0;
#pragma unroll
        for (int i = 0; i < HW / (4 * NT); i++) {
            float4 v = xin[tid + i * NT];
            float vv[4] = {v.x, v.y, v.z, v.w};
#pragma unroll
            for (int j = 0; j < 4; j++) {
                unsigned kk = f2key(vv[j]);
                if (kk > T) { ls += vv[j]; lc++; }
            }
        }
#pragma unroll
        for (int o = 16; o; o >>= 1) {
            ls += __shfl_down_sync(0xffffffffu, ls, o);
            lc += __shfl_down_sync(0xffffffffu, lc, o);
        }
        if (lane == 0) { fred[w] = ls; ired[w] = lc; }
        __syncthreads();
        if (tid == 0) {
            float s = 0.f; int c = 0;
            for (int i = 0; i < NWARP; i++) { s += fred[i]; c += ired[i]; }
            g_avg[row] = (s + key2f(T) * (float)(TOPK - c)) / (float)TOPK;
        }
    }
}

// ---------------------------------------------------------------------------
// Kernel 3: tiny per-batch MLP -> g_scale
// ---------------------------------------------------------------------------
__global__ void mlp_kernel(const float* __restrict__ w1, const float* __restrict__ b1,
                           const float* __restrict__ w2, const float* __restrict__ b2) {
    __shared__ float avg[CC], mx[CC], h[2 * HID];
    const int b = blockIdx.x, c = threadIdx.x;
    avg[c] = g_avg[b * CC + c];
    mx[c]  = g_maxv[b * CC + c];
    __syncthreads();
    if (c < 2 * HID) {
        int j = c & (HID - 1);
        const float* pool = (c < HID) ? avg : mx;
        float s = b1[j];
#pragma unroll 8
        for (int i = 0; i < CC; i++) s += pool[i] * w1[i * HID + j];
        h[c] = fmaxf(s, 0.f);
    }
    __syncthreads();
    float s = 2.f * b2[c];
#pragma unroll
    for (int j = 0; j < HID; j++) s += (h[j] + h[HID + j]) * w2[j * CC + c];
    g_scale[b * CC + c] = 1.f / (1.f + __expf(-s));
}

// ---------------------------------------------------------------------------
// Kernel 4: y = x * scale[row]
// ---------------------------------------------------------------------------
__global__ __launch_bounds__(256) void scale_kernel(const float* __restrict__ x,
                                                    float* __restrict__ y) {
    const int row = blockIdx.x;
    const float s = g_scale[row];
    const float4* xi = (const float4*)(x + (size_t)row * HW);
    float4* yo = (float4*)(y + (size_t)row * HW);
    const int t = threadIdx.x;
#pragma unroll
    for (int i = 0; i < HW / (4 * 256); i++) {
        float4 v = xi[t + i * 256];
        v.x *= s; v.y *= s; v.z *= s; v.w *= s;
        yo[t + i * 256] = v;
    }
}

extern "C" void kernel_launch(void* const* d_in, const int* in_sizes, int n_in,
                              void* d_out, int out_size) {
    const float* x  = (const float*)d_in[0];
    const float* w1 = (const float*)d_in[1];
    const float* b1 = (const float*)d_in[2];
    const float* w2 = (const float*)d_in[3];
    const float* b2 = (const float*)d_in[4];
    float* y = (float*)d_out;

    topk_compact<<<ROWS, NT>>>(x);
    topk_select<<<ROWS, NT>>>(x);
    mlp_kernel<<<BB, CC>>>(w1, b1, w2, b2);
    scale_kernel<<<ROWS, 256>>>(x, y);
}

// round 7
// speedup vs baseline: 1.0484x; 1.0484x over previous
#include <cuda_runtime.h>

#define HW    16384      // H*W
#define ROWS  4096       // B*C
#define CC    128
#define BB    32
#define TOPK  1638       // round(16384 * 0.1)
#define HID   8
#define NT    512
#define NWARP 16
#define NB    2048       // 11-bit bins (levels 1,2)
#define NB3   1024       // 10-bit final bins
#define SLOT  16         // per-thread candidate slots
#define STRIDE 17        // padded stride (gcd(17,32)=1 -> spread banks)
#define T_LO  1.0f

__device__ float g_avg[ROWS];
__device__ float g_maxv[ROWS];
__device__ float g_scale[ROWS];

// Order-preserving float->uint key (general, used only in fallback)
__device__ __forceinline__ unsigned f2key(float f) {
    unsigned u = __float_as_uint(f);
    return u ^ ((unsigned)((int)u >> 31) | 0x80000000u);
}
__device__ __forceinline__ float key2f(unsigned k) {
    unsigned u = k ^ (((int)k < 0) ? 0x80000000u : 0xFFFFFFFFu);
    return __uint_as_float(u);
}

// Warp-aggregated histogram increment; d == -1 means skip. Full-warp, converged.
__device__ __forceinline__ void agg_add(int* h, int d) {
    unsigned m = __match_any_sync(0xffffffffu, d);
    if (d >= 0 && (int)(threadIdx.x & 31) == __ffs((int)m) - 1)
        atomicAdd(&h[d], __popc(m));
}

// Suffix-count select: bin b with s(b) >= rem > s(b+1), s(b)=sum_{j>=b} h[j].
// Warp-parallel cross-warp combine (no serial thread-0 loop).
template <int BPT>
__device__ __forceinline__ void suffix_select(const int* h, int rem,
                                              int* swarp, unsigned* sdigit,
                                              int* srem) {
    const int tid = threadIdx.x, lane = tid & 31, w = tid >> 5;
    const int base = tid * BPT;
    int loc[BPT];
    int tsum = 0;
#pragma unroll
    for (int i = 0; i < BPT; i++) { loc[i] = h[base + i]; tsum += loc[i]; }
    int inc = tsum;                       // suffix over lanes >= lane
#pragma unroll
    for (int o = 1; o < 32; o <<= 1) {
        int v = __shfl_down_sync(0xffffffffu, inc, o);
        if (lane + o < 32) inc += v;
    }
    if (lane == 0) swarp[w] = inc;
    __syncthreads();
    if (tid < 32) {                       // warp-parallel combine over 16 warp sums
        int v = (lane < NWARP) ? swarp[lane] : 0;
        int s = v;
#pragma unroll
        for (int o = 1; o < 32; o <<= 1) {
            int t = __shfl_down_sync(0xffffffffu, s, o);
            if (lane + o < 32) s += t;
        }
        if (lane < NWARP) swarp[lane] = s - v;   // exclusive suffix (warps above)
    }
    __syncthreads();
    int s_next = (inc - tsum) + swarp[w];
#pragma unroll
    for (int i = BPT - 1; i >= 0; i--) {
        int s = loc[i] + s_next;
        if (s >= rem && s_next < rem) { *sdigit = (unsigned)(base + i); *srem = rem - s_next; }
        s_next = s;
    }
    __syncthreads();
}

// ---------------------------------------------------------------------------
// Pass 1: per-(b,c) top-k mean + max. Cheap per-thread compaction sweep, then
// 3-level radix select on the ~2600 candidates (all > T_LO, hence positive).
// ---------------------------------------------------------------------------
__global__ __launch_bounds__(NT) void topk_stats(const float* __restrict__ x) {
    __shared__ float    cand[NT * STRIDE];   // ~34.8 KB, per-thread segments
    __shared__ int      hist[NB];            // 8 KB
    __shared__ float    shist[NB3];          // 4 KB
    __shared__ int      swarp[NWARP];
    __shared__ unsigned sdigit;
    __shared__ int      srem, sfall;
    __shared__ float    fred[NWARP];
    __shared__ int      ired[NWARP];

    const int tid = threadIdx.x, lane = tid & 31, w = tid >> 5;
    const int row = blockIdx.x;
    const float4* xin = (const float4*)(x + (size_t)row * HW);
    float* seg = cand + tid * STRIDE;

    // ---- sweep: row max + per-thread compaction (no cross-lane ops) ----
    int cnt = 0;
    float lmax = -3.402823466e38f;
#pragma unroll
    for (int i = 0; i < HW / (4 * NT); i++) {
        float4 v = xin[tid + i * NT];
        lmax = fmaxf(lmax, fmaxf(fmaxf(v.x, v.y), fmaxf(v.z, v.w)));
        if (v.x > T_LO) { if (cnt < SLOT) seg[cnt] = v.x; cnt++; }
        if (v.y > T_LO) { if (cnt < SLOT) seg[cnt] = v.y; cnt++; }
        if (v.z > T_LO) { if (cnt < SLOT) seg[cnt] = v.z; cnt++; }
        if (v.w > T_LO) { if (cnt < SLOT) seg[cnt] = v.w; cnt++; }
    }
    // max + count + overflow block reduction
    int of = (cnt > SLOT) ? 1 : 0;
    int tot = cnt;
#pragma unroll
    for (int o = 16; o; o >>= 1) {
        lmax = fmaxf(lmax, __shfl_down_sync(0xffffffffu, lmax, o));
        tot += __shfl_down_sync(0xffffffffu, tot, o);
        of  |= __shfl_down_sync(0xffffffffu, of, o);
    }
    if (lane == 0) { fred[w] = lmax; ired[w] = tot; swarp[w] = of; }
    __syncthreads();
    if (tid == 0) {
        float m = fred[0]; int t = 0, o = 0;
        for (int i = 0; i < NWARP; i++) { m = fmaxf(m, fred[i]); t += ired[i]; o |= swarp[i]; }
        g_maxv[row] = m;
        sfall = (o || t < TOPK);
    }
    __syncthreads();

    if (!sfall) {
        // load own slots into registers (bits are monotonic: all values > 1 > 0)
        const int myc = cnt;              // <= SLOT here
        unsigned kb[SLOT];
#pragma unroll
        for (int i = 0; i < SLOT; i++) kb[i] = __float_as_uint(seg[i]);

        // ---- L1: top 11 bits ----
        for (int i = tid; i < NB; i += NT) hist[i] = 0;
        __syncthreads();
#pragma unroll
        for (int i = 0; i < SLOT; i++)
            agg_add(hist, (i < myc) ? (int)(kb[i] >> 21) : -1);
        __syncthreads();
        suffix_select<NB / NT>(hist, TOPK, swarp, &sdigit, &srem);
        const unsigned d0 = sdigit; const int rem1 = srem;

        // ---- L2: next 11 bits ----
        for (int i = tid; i < NB; i += NT) hist[i] = 0;
        __syncthreads();
#pragma unroll
        for (int i = 0; i < SLOT; i++)
            agg_add(hist, (i < myc && (kb[i] >> 21) == d0)
                              ? (int)((kb[i] >> 10) & (NB - 1)) : -1);
        __syncthreads();
        suffix_select<NB / NT>(hist, rem1, swarp, &sdigit, &srem);
        const unsigned P1 = (d0 << 11) | sdigit; const int rem2 = srem;

        // ---- L3: final 10 bits; count + value-sum hists on sparse hits ----
        for (int i = tid; i < NB3; i += NT) { hist[i] = 0; shist[i] = 0.f; }
        __syncthreads();
        float lsum = 0.f;
#pragma unroll
        for (int i = 0; i < SLOT; i++) {
            if (i < myc) {
                unsigned t = kb[i] >> 10;
                if (t > P1) lsum += __uint_as_float(kb[i]);
                else if (t == P1) {
                    atomicAdd(&hist[kb[i] & (NB3 - 1)], 1);
                    atomicAdd(&shist[kb[i] & (NB3 - 1)], __uint_as_float(kb[i]));
                }
            }
        }
        __syncthreads();
        suffix_select<NB3 / NT>(hist, rem2, swarp, &sdigit, &srem);
        const unsigned d2 = sdigit; const int ties = srem;

        float sa = 0.f;
        for (int b = tid; b < NB3; b += NT)
            if (b > (int)d2) sa += shist[b];
        float acc = lsum + sa;
#pragma unroll
        for (int o = 16; o; o >>= 1) acc += __shfl_down_sync(0xffffffffu, acc, o);
        if (lane == 0) fred[w] = acc;
        __syncthreads();
        if (tid == 0) {
            float s = 0.f;
            for (int i = 0; i < NWARP; i++) s += fred[i];
            float Tv = __uint_as_float((P1 << 10) | d2);
            g_avg[row] = (s + Tv * (float)ties) / (float)TOPK;
        }
    } else {
        // ---- exact fallback: bitwise binary search for k-th largest key ----
        unsigned T = 0u;
        for (int bit = 31; bit >= 0; --bit) {
            const unsigned cT = T | (1u << bit);
            int c = 0;
#pragma unroll
            for (int i = 0; i < HW / (4 * NT); i++) {
                float4 v = xin[tid + i * NT];
                c += (f2key(v.x) >= cT) + (f2key(v.y) >= cT)
                   + (f2key(v.z) >= cT) + (f2key(v.w) >= cT);
            }
#pragma unroll
            for (int o = 16; o; o >>= 1) c += __shfl_down_sync(0xffffffffu, c, o);
            if (lane == 0) ired[w] = c;
            __syncthreads();
            if (tid == 0) {
                int s = 0;
                for (int i = 0; i < NWARP; i++) s += ired[i];
                srem = s;
            }
            __syncthreads();
            if (srem >= TOPK) T = cT;
            __syncthreads();
        }
        float ls = 0.f; int lc = 0;
#pragma unroll
        for (int i = 0; i < HW / (4 * NT); i++) {
            float4 v = xin[tid + i * NT];
            float vv[4] = {v.x, v.y, v.z, v.w};
#pragma unroll
            for (int j = 0; j < 4; j++) {
                unsigned kk = f2key(vv[j]);
                if (kk > T) { ls += vv[j]; lc++; }
            }
        }
#pragma unroll
        for (int o = 16; o; o >>= 1) {
            ls += __shfl_down_sync(0xffffffffu, ls, o);
            lc += __shfl_down_sync(0xffffffffu, lc, o);
        }
        if (lane == 0) { fred[w] = ls; ired[w] = lc; }
        __syncthreads();
        if (tid == 0) {
            float s = 0.f; int c = 0;
            for (int i = 0; i < NWARP; i++) { s += fred[i]; c += ired[i]; }
            g_avg[row] = (s + key2f(T) * (float)(TOPK - c)) / (float)TOPK;
        }
    }
}

// ---------------------------------------------------------------------------
// Kernel 2: tiny per-batch MLP -> g_scale
// ---------------------------------------------------------------------------
__global__ void mlp_kernel(const float* __restrict__ w1, const float* __restrict__ b1,
                           const float* __restrict__ w2, const float* __restrict__ b2) {
    __shared__ float avg[CC], mx[CC], h[2 * HID];
    const int b = blockIdx.x, c = threadIdx.x;
    avg[c] = g_avg[b * CC + c];
    mx[c]  = g_maxv[b * CC + c];
    __syncthreads();
    if (c < 2 * HID) {
        int j = c & (HID - 1);
        const float* pool = (c < HID) ? avg : mx;
        float s = b1[j];
#pragma unroll 8
        for (int i = 0; i < CC; i++) s += pool[i] * w1[i * HID + j];
        h[c] = fmaxf(s, 0.f);
    }
    __syncthreads();
    float s = 2.f * b2[c];
#pragma unroll
    for (int j = 0; j < HID; j++) s += (h[j] + h[HID + j]) * w2[j * CC + c];
    g_scale[b * CC + c] = 1.f / (1.f + __expf(-s));
}

// ---------------------------------------------------------------------------
// Kernel 3: y = x * scale[row]
// ---------------------------------------------------------------------------
__global__ __launch_bounds__(256) void scale_kernel(const float* __restrict__ x,
                                                    float* __restrict__ y) {
    const int row = blockIdx.x;
    const float s = g_scale[row];
    const float4* xi = (const float4*)(x + (size_t)row * HW);
    float4* yo = (float4*)(y + (size_t)row * HW);
    const int t = threadIdx.x;
#pragma unroll
    for (int i = 0; i < HW / (4 * 256); i++) {
        float4 v = xi[t + i * 256];
        v.x *= s; v.y *= s; v.z *= s; v.w *= s;
        yo[t + i * 256] = v;
    }
}

extern "C" void kernel_launch(void* const* d_in, const int* in_sizes, int n_in,
                              void* d_out, int out_size) {
    const float* x  = (const float*)d_in[0];
    const float* w1 = (const float*)d_in[1];
    const float* b1 = (const float*)d_in[2];
    const float* w2 = (const float*)d_in[3];
    const float* b2 = (const float*)d_in[4];
    float* y = (float*)d_out;

    topk_stats<<<ROWS, NT>>>(x);
    mlp_kernel<<<BB, CC>>>(w1, b1, w2, b2);
    scale_kernel<<<ROWS, 256>>>(x, y);
}

// round 8
// speedup vs baseline: 1.6725x; 1.5953x over previous
#include <cuda_runtime.h>

#define HW    16384      // H*W
#define ROWS  4096       // B*C
#define CC    128
#define BB    32
#define TOPK  1638       // round(16384 * 0.1)
#define HID   8
#define NT    256
#define NWARP 8
#define SLOT  32         // per-thread candidate slots (64 elems/thread, ~10 hits)
#define STRIDE 33        // padded stride
#define NBH   1792       // L1 bins (7 per thread); valid range [0,1536]
#define BUFN  256        // threshold-bin buffer
#define T_LO  1.0f
#define FONE  0x3F800000u

__device__ float g_avg[ROWS];
__device__ float g_maxv[ROWS];
__device__ float g_scale[ROWS];

__device__ __forceinline__ unsigned f2key(float f) {
    unsigned u = __float_as_uint(f);
    return u ^ ((unsigned)((int)u >> 31) | 0x80000000u);
}
__device__ __forceinline__ float key2f(unsigned k) {
    unsigned u = k ^ (((int)k < 0) ? 0x80000000u : 0xFFFFFFFFu);
    return __uint_as_float(u);
}

// Suffix-count select over NBH bins: bin b with s(b) >= rem > s(b+1).
template <int BPT>
__device__ __forceinline__ void suffix_select(const int* h, int rem,
                                              int* swarp, unsigned* sdigit,
                                              int* srem) {
    const int tid = threadIdx.x, lane = tid & 31, w = tid >> 5;
    const int base = tid * BPT;
    int loc[BPT];
    int tsum = 0;
#pragma unroll
    for (int i = 0; i < BPT; i++) { loc[i] = h[base + i]; tsum += loc[i]; }
    int inc = tsum;                       // suffix over lanes >= lane
#pragma unroll
    for (int o = 1; o < 32; o <<= 1) {
        int v = __shfl_down_sync(0xffffffffu, inc, o);
        if (lane + o < 32) inc += v;
    }
    if (lane == 0) swarp[w] = inc;
    __syncthreads();
    if (tid < 32) {
        int v = (lane < NWARP) ? swarp[lane] : 0;
        int s = v;
#pragma unroll
        for (int o = 1; o < 32; o <<= 1) {
            int t = __shfl_down_sync(0xffffffffu, s, o);
            if (lane + o < 32) s += t;
        }
        if (lane < NWARP) swarp[lane] = s - v;   // exclusive suffix above this warp
    }
    __syncthreads();
    int s_next = (inc - tsum) + swarp[w];
#pragma unroll
    for (int i = BPT - 1; i >= 0; i--) {
        int s = loc[i] + s_next;
        if (s >= rem && s_next < rem) { *sdigit = (unsigned)(base + i); *srem = rem - s_next; }
        s_next = s;
    }
    __syncthreads();
}

// ---------------------------------------------------------------------------
// Pass 1: per-(b,c) top-k mean + max. Per-thread compaction sweep, then ONE
// 1536-bin histogram level + 14-bit in-bin binary search (warp 0).
// ---------------------------------------------------------------------------
__global__ __launch_bounds__(NT, 4) void topk_stats(const float* __restrict__ x) {
    __shared__ float    cand[NT * STRIDE];   // 33 KB per-thread segments
    __shared__ int      hist[NBH];           // 7 KB
    __shared__ unsigned buf[BUFN];           // 1 KB threshold-bin members (low 14 bits)
    __shared__ int      swarp[NWARP];
    __shared__ unsigned sdigit, suT;
    __shared__ int      srem, sfall, snb;
    __shared__ float    fred[NWARP];
    __shared__ int      ired[NWARP];

    const int tid = threadIdx.x, lane = tid & 31, w = tid >> 5;
    const int row = blockIdx.x;
    const float4* xin = (const float4*)(x + (size_t)row * HW);
    float* seg = cand + tid * STRIDE;

    // ---- sweep: row max + per-thread compaction (no cross-lane ops) ----
    int cnt = 0;
    float lmax = -3.402823466e38f;
#pragma unroll 8
    for (int i = 0; i < HW / (4 * NT); i++) {
        float4 v = xin[tid + i * NT];
        lmax = fmaxf(lmax, fmaxf(fmaxf(v.x, v.y), fmaxf(v.z, v.w)));
        if (v.x > T_LO) { if (cnt < SLOT) seg[cnt] = v.x; cnt++; }
        if (v.y > T_LO) { if (cnt < SLOT) seg[cnt] = v.y; cnt++; }
        if (v.z > T_LO) { if (cnt < SLOT) seg[cnt] = v.z; cnt++; }
        if (v.w > T_LO) { if (cnt < SLOT) seg[cnt] = v.w; cnt++; }
    }
    int of = (cnt > SLOT) ? 1 : 0;
    int tot = cnt;
#pragma unroll
    for (int o = 16; o; o >>= 1) {
        lmax = fmaxf(lmax, __shfl_down_sync(0xffffffffu, lmax, o));
        tot += __shfl_down_sync(0xffffffffu, tot, o);
        of  |= __shfl_down_sync(0xffffffffu, of, o);
    }
    if (lane == 0) { fred[w] = lmax; ired[w] = tot; swarp[w] = of; }
    __syncthreads();
    if (tid == 0) {
        float m = fred[0]; int t = 0, o = 0;
        for (int i = 0; i < NWARP; i++) { m = fmaxf(m, fred[i]); t += ired[i]; o |= swarp[i]; }
        g_maxv[row] = m;
        sfall = (o || t < TOPK);
        snb = 0;
    }
    __syncthreads();

    if (!sfall) {
        // ---- single histogram level: bin = (u - 1.0f_bits) >> 14, clamp ----
        for (int i = tid; i < NBH; i += NT) hist[i] = 0;
        __syncthreads();
        for (int i = 0; i < cnt; i++) {
            unsigned u = __float_as_uint(seg[i]);
            int b = min((int)((u - FONE) >> 14), 1536);
            atomicAdd(&hist[b], 1);
        }
        __syncthreads();
        suffix_select<NBH / NT>(hist, TOPK, swarp, &sdigit, &srem);
        const unsigned d0 = sdigit; const int rem1 = srem;

        if (d0 >= 1536) { if (tid == 0) sfall = 1; }
        else {
            // collect threshold-bin members (low 14 bits) into buf
            for (int i = 0; i < cnt; i++) {
                unsigned u = __float_as_uint(seg[i]);
                if ((u - FONE) >> 14 == d0) {
                    int p = atomicAdd(&snb, 1);
                    if (p < BUFN) buf[p] = u & 0x3FFFu;
                }
            }
            __syncthreads();
            if (snb > BUFN) { if (tid == 0) sfall = 1; }
            else if (w == 0) {
                // warp 0: bitwise binary search over low 14 bits for rem1-th largest
                const int nb = snb;
                const int nj = (nb + 31) >> 5;
                unsigned my[BUFN / 32];
                for (int j = 0; j < nj; j++)
                    my[j] = (lane + 32 * j < nb) ? buf[lane + 32 * j] : 0u;
                unsigned T = 0u;
#pragma unroll
                for (int bit = 13; bit >= 0; --bit) {
                    unsigned cT = T | (1u << bit);
                    int c = 0;
                    for (int j = 0; j < nj; j++)
                        c += __popc(__ballot_sync(0xffffffffu, my[j] >= cT));
                    if (c >= rem1) T = cT;
                }
                if (lane == 0) suT = FONE | (d0 << 14) | T;
            }
        }
        __syncthreads();

        if (!sfall) {
            // ---- final: sum/count of values strictly above threshold ----
            const float Tval = __uint_as_float(suT);
            float ls = 0.f; int lc = 0;
            for (int i = 0; i < cnt; i++) {
                float v = seg[i];
                if (v > Tval) { ls += v; lc++; }
            }
#pragma unroll
            for (int o = 16; o; o >>= 1) {
                ls += __shfl_down_sync(0xffffffffu, ls, o);
                lc += __shfl_down_sync(0xffffffffu, lc, o);
            }
            if (lane == 0) { fred[w] = ls; ired[w] = lc; }
            __syncthreads();
            if (tid == 0) {
                float s = 0.f; int c = 0;
                for (int i = 0; i < NWARP; i++) { s += fred[i]; c += ired[i]; }
                g_avg[row] = (s + Tval * (float)(TOPK - c)) / (float)TOPK;
            }
            return;
        }
    }

    // ---- exact fallback: bitwise binary search over full 32-bit keys ----
    {
        unsigned T = 0u;
        for (int bit = 31; bit >= 0; --bit) {
            const unsigned cT = T | (1u << bit);
            int c = 0;
#pragma unroll 4
            for (int i = 0; i < HW / (4 * NT); i++) {
                float4 v = xin[tid + i * NT];
                c += (f2key(v.x) >= cT) + (f2key(v.y) >= cT)
                   + (f2key(v.z) >= cT) + (f2key(v.w) >= cT);
            }
#pragma unroll
            for (int o = 16; o; o >>= 1) c += __shfl_down_sync(0xffffffffu, c, o);
            if (lane == 0) ired[w] = c;
            __syncthreads();
            if (tid == 0) {
                int s = 0;
                for (int i = 0; i < NWARP; i++) s += ired[i];
                srem = s;
            }
            __syncthreads();
            if (srem >= TOPK) T = cT;
            __syncthreads();
        }
        float ls = 0.f; int lc = 0;
#pragma unroll 4
        for (int i = 0; i < HW / (4 * NT); i++) {
            float4 v = xin[tid + i * NT];
            float vv[4] = {v.x, v.y, v.z, v.w};
#pragma unroll
            for (int j = 0; j < 4; j++) {
                unsigned kk = f2key(vv[j]);
                if (kk > T) { ls += vv[j]; lc++; }
            }
        }
#pragma unroll
        for (int o = 16; o; o >>= 1) {
            ls += __shfl_down_sync(0xffffffffu, ls, o);
            lc += __shfl_down_sync(0xffffffffu, lc, o);
        }
        if (lane == 0) { fred[w] = ls; ired[w] = lc; }
        __syncthreads();
        if (tid == 0) {
            float s = 0.f; int c = 0;
            for (int i = 0; i < NWARP; i++) { s += fred[i]; c += ired[i]; }
            g_avg[row] = (s + key2f(T) * (float)(TOPK - c)) / (float)TOPK;
        }
    }
}

// ---------------------------------------------------------------------------
// Kernel 2: tiny per-batch MLP -> g_scale
// ---------------------------------------------------------------------------
__global__ void mlp_kernel(const float* __restrict__ w1, const float* __restrict__ b1,
                           const float* __restrict__ w2, const float* __restrict__ b2) {
    __shared__ float avg[CC], mx[CC], h[2 * HID];
    const int b = blockIdx.x, c = threadIdx.x;
    avg[c] = g_avg[b * CC + c];
    mx[c]  = g_maxv[b * CC + c];
    __syncthreads();
    if (c < 2 * HID) {
        int j = c & (HID - 1);
        const float* pool = (c < HID) ? avg : mx;
        float s = b1[j];
#pragma unroll 8
        for (int i = 0; i < CC; i++) s += pool[i] * w1[i * HID + j];
        h[c] = fmaxf(s, 0.f);
    }
    __syncthreads();
    float s = 2.f * b2[c];
#pragma unroll
    for (int j = 0; j < HID; j++) s += (h[j] + h[HID + j]) * w2[j * CC + c];
    g_scale[b * CC + c] = 1.f / (1.f + __expf(-s));
}

// ---------------------------------------------------------------------------
// Kernel 3: y = x * scale[row]
// ---------------------------------------------------------------------------
__global__ __launch_bounds__(256) void scale_kernel(const float* __restrict__ x,
                                                    float* __restrict__ y) {
    const int row = blockIdx.x;
    const float s = g_scale[row];
    const float4* xi = (const float4*)(x + (size_t)row * HW);
    float4* yo = (float4*)(y + (size_t)row * HW);
    const int t = threadIdx.x;
#pragma unroll
    for (int i = 0; i < HW / (4 * 256); i++) {
        float4 v = xi[t + i * 256];
        v.x *= s; v.y *= s; v.z *= s; v.w *= s;
        yo[t + i * 256] = v;
    }
}

extern "C" void kernel_launch(void* const* d_in, const int* in_sizes, int n_in,
                              void* d_out, int out_size) {
    const float* x  = (const float*)d_in[0];
    const float* w1 = (const float*)d_in[1];
    const float* b1 = (const float*)d_in[2];
    const float* w2 = (const float*)d_in[3];
    const float* b2 = (const float*)d_in[4];
    float* y = (float*)d_out;

    topk_stats<<<ROWS, NT>>>(x);
    mlp_kernel<<<BB, CC>>>(w1, b1, w2, b2);
    scale_kernel<<<ROWS, 256>>>(x, y);
}

// round 10
// speedup vs baseline: 1.7146x; 1.0252x over previous
#include <cuda_runtime.h>

#define HW    16384      // H*W
#define ROWS  4096       // B*C
#define CC    128
#define BB    32
#define TOPK  1638       // round(16384 * 0.1)
#define HID   8
#define NT    256
#define NWARP 8
#define SLOT  28         // per-thread candidate slots (64 elems/thread, ~10 hits)
#define STRIDE 29        // padded stride
#define NBH   1792       // histogram bins (7/thread); valid ids [0,1536]
#define BUFN  256        // threshold-bin buffer
#define T_LO  1.0f
#define FONE  0x3F800000u

__device__ float g_avg[ROWS];
__device__ float g_maxv[ROWS];
__device__ float g_scale[ROWS];

__device__ __forceinline__ unsigned f2key(float f) {
    unsigned u = __float_as_uint(f);
    return u ^ ((unsigned)((int)u >> 31) | 0x80000000u);
}
__device__ __forceinline__ float key2f(unsigned k) {
    unsigned u = k ^ (((int)k < 0) ? 0x80000000u : 0xFFFFFFFFu);
    return __uint_as_float(u);
}
__device__ __forceinline__ int vbin(float v) {
    return min((int)((__float_as_uint(v) - FONE) >> 14), 1536);
}

// Suffix-count select: bin b with s(b) >= rem > s(b+1), s(b)=sum_{j>=b} h[j].
template <int BPT>
__device__ __forceinline__ void suffix_select(const int* h, int rem,
                                              int* swarp, unsigned* sdigit,
                                              int* srem) {
    const int tid = threadIdx.x, lane = tid & 31, w = tid >> 5;
    const int base = tid * BPT;
    int loc[BPT];
    int tsum = 0;
#pragma unroll
    for (int i = 0; i < BPT; i++) { loc[i] = h[base + i]; tsum += loc[i]; }
    int inc = tsum;                       // suffix over lanes >= lane
#pragma unroll
    for (int o = 1; o < 32; o <<= 1) {
        int v = __shfl_down_sync(0xffffffffu, inc, o);
        if (lane + o < 32) inc += v;
    }
    if (lane == 0) swarp[w] = inc;
    __syncthreads();
    if (tid < 32) {
        int v = (lane < NWARP) ? swarp[lane] : 0;
        int s = v;
#pragma unroll
        for (int o = 1; o < 32; o <<= 1) {
            int t = __shfl_down_sync(0xffffffffu, s, o);
            if (lane + o < 32) s += t;
        }
        if (lane < NWARP) swarp[lane] = s - v;   // exclusive suffix above this warp
    }
    __syncthreads();
    int s_next = (inc - tsum) + swarp[w];
#pragma unroll
    for (int i = BPT - 1; i >= 0; i--) {
        int s = loc[i] + s_next;
        if (s >= rem && s_next < rem) { *sdigit = (unsigned)(base + i); *srem = rem - s_next; }
        s_next = s;
    }
    __syncthreads();
}

// ---------------------------------------------------------------------------
// Pass 1: per-(b,c) top-k mean + max. Sweep fuses compaction + histogram;
// then one suffix-select + 14-bit in-bin binary search (warp 0).
// ---------------------------------------------------------------------------
__global__ __launch_bounds__(NT, 5) void topk_stats(const float* __restrict__ x) {
    __shared__ float    cand[NT * STRIDE];   // 29 KB per-thread segments
    __shared__ int      hist[NBH];           // 7 KB
    __shared__ unsigned buf[BUFN];           // 1 KB threshold-bin members (low 14 bits)
    __shared__ int      swarp[NWARP];
    __shared__ unsigned sdigit, suT;
    __shared__ int      srem, sfall, snb;
    __shared__ float    fred[NWARP];
    __shared__ int      ired[NWARP];

    const int tid = threadIdx.x, lane = tid & 31, w = tid >> 5;
    const int row = blockIdx.x;
    const float4* xin = (const float4*)(x + (size_t)row * HW);
    float* seg = cand + tid * STRIDE;

    // zero histogram BEFORE sweep (sweep atomically increments it)
#pragma unroll
    for (int i = 0; i < NBH / NT; i++) hist[tid + i * NT] = 0;
    if (tid == 0) snb = 0;
    __syncthreads();

    // ---- sweep: row max + per-thread compaction + fused histogram ----
    int cnt = 0;
    float lmax = -3.402823466e38f;
#pragma unroll 8
    for (int i = 0; i < HW / (4 * NT); i++) {
        float4 v = xin[tid + i * NT];
        lmax = fmaxf(lmax, fmaxf(fmaxf(v.x, v.y), fmaxf(v.z, v.w)));
        int h0 = v.x > T_LO, h1 = v.y > T_LO, h2 = v.z > T_LO, h3 = v.w > T_LO;
        int p0 = cnt, p1 = p0 + h0, p2 = p1 + h1, p3 = p2 + h2;
        if (h0) { if (p0 < SLOT) seg[p0] = v.x; atomicAdd(&hist[vbin(v.x)], 1); }
        if (h1) { if (p1 < SLOT) seg[p1] = v.y; atomicAdd(&hist[vbin(v.y)], 1); }
        if (h2) { if (p2 < SLOT) seg[p2] = v.z; atomicAdd(&hist[vbin(v.z)], 1); }
        if (h3) { if (p3 < SLOT) seg[p3] = v.w; atomicAdd(&hist[vbin(v.w)], 1); }
        cnt = p3 + h3;                         // one serial add per float4
    }
    int of = (cnt > SLOT) ? 1 : 0;
    int tot = cnt;
#pragma unroll
    for (int o = 16; o; o >>= 1) {
        lmax = fmaxf(lmax, __shfl_down_sync(0xffffffffu, lmax, o));
        tot += __shfl_down_sync(0xffffffffu, tot, o);
        of  |= __shfl_down_sync(0xffffffffu, of, o);
    }
    if (lane == 0) { fred[w] = lmax; ired[w] = tot; swarp[w] = of; }
    __syncthreads();
    if (tid == 0) {
        float m = fred[0]; int t = 0, o = 0;
        for (int i = 0; i < NWARP; i++) { m = fmaxf(m, fred[i]); t += ired[i]; o |= swarp[i]; }
        g_maxv[row] = m;
        sfall = (o || t < TOPK);
    }
    __syncthreads();

    if (!sfall) {
        suffix_select<NBH / NT>(hist, TOPK, swarp, &sdigit, &srem);
        const unsigned d0 = sdigit; const int rem1 = srem;

        if (d0 >= 1536) { if (tid == 0) sfall = 1; }
        else {
            // collect threshold-bin members (low 14 bits) into buf
            for (int i = 0; i < cnt; i++) {
                unsigned u = __float_as_uint(seg[i]);
                if ((u - FONE) >> 14 == d0) {
                    int p = atomicAdd(&snb, 1);
                    if (p < BUFN) buf[p] = u & 0x3FFFu;
                }
            }
            __syncthreads();
            if (snb > BUFN) { if (tid == 0) sfall = 1; }
            else if (w == 0) {
                // warp 0: bitwise binary search over low 14 bits for rem1-th largest
                const int nb = snb;
                const int nj = (nb + 31) >> 5;
                unsigned my[BUFN / 32];
                for (int j = 0; j < nj; j++)
                    my[j] = (lane + 32 * j < nb) ? buf[lane + 32 * j] : 0u;
                unsigned T = 0u;
#pragma unroll
                for (int bit = 13; bit >= 0; --bit) {
                    unsigned cT = T | (1u << bit);
                    int c = 0;
                    for (int j = 0; j < nj; j++)
                        c += __popc(__ballot_sync(0xffffffffu, my[j] >= cT));
                    if (c >= rem1) T = cT;
                }
                if (lane == 0) suT = FONE | (d0 << 14) | T;
            }
        }
        __syncthreads();

        if (!sfall) {
            // ---- final: sum/count of candidates strictly above threshold ----
            const float Tval = __uint_as_float(suT);
            float ls = 0.f; int lc = 0;
            for (int i = 0; i < cnt; i++) {
                float v = seg[i];
                if (v > Tval) { ls += v; lc++; }
            }
#pragma unroll
            for (int o = 16; o; o >>= 1) {
                ls += __shfl_down_sync(0xffffffffu, ls, o);
                lc += __shfl_down_sync(0xffffffffu, lc, o);
            }
            if (lane == 0) { fred[w] = ls; ired[w] = lc; }
            __syncthreads();
            if (tid == 0) {
                float s = 0.f; int c = 0;
                for (int i = 0; i < NWARP; i++) { s += fred[i]; c += ired[i]; }
                g_avg[row] = (s + Tval * (float)(TOPK - c)) / (float)TOPK;
            }
            return;
        }
    }

    // ---- exact fallback: bitwise binary search over full 32-bit keys ----
    {
        unsigned T = 0u;
        for (int bit = 31; bit >= 0; --bit) {
            const unsigned cT = T | (1u << bit);
            int c = 0;
#pragma unroll 4
            for (int i = 0; i < HW / (4 * NT); i++) {
                float4 v = xin[tid + i * NT];
                c += (f2key(v.x) >= cT) + (f2key(v.y) >= cT)
                   + (f2key(v.z) >= cT) + (f2key(v.w) >= cT);
            }
#pragma unroll
            for (int o = 16; o; o >>= 1) c += __shfl_down_sync(0xffffffffu, c, o);
            if (lane == 0) ired[w] = c;
            __syncthreads();
            if (tid == 0) {
                int s = 0;
                for (int i = 0; i < NWARP; i++) s += ired[i];
                srem = s;
            }
            __syncthreads();
            if (srem >= TOPK) T = cT;
            __syncthreads();
        }
        float ls = 0.f; int lc = 0;
#pragma unroll 4
        for (int i = 0; i < HW / (4 * NT); i++) {
            float4 v = xin[tid + i * NT];
            float vv[4] = {v.x, v.y, v.z, v.w};
#pragma unroll
            for (int j = 0; j < 4; j++) {
                unsigned kk = f2key(vv[j]);
                if (kk > T) { ls += vv[j]; lc++; }
            }
        }
#pragma unroll
        for (int o = 16; o; o >>= 1) {
            ls += __shfl_down_sync(0xffffffffu, ls, o);
            lc += __shfl_down_sync(0xffffffffu, lc, o);
        }
        if (lane == 0) { fred[w] = ls; ired[w] = lc; }
        __syncthreads();
        if (tid == 0) {
            float s = 0.f; int c = 0;
            for (int i = 0; i < NWARP; i++) { s += fred[i]; c += ired[i]; }
            g_avg[row] = (s + key2f(T) * (float)(TOPK - c)) / (float)TOPK;
        }
    }
}

// ---------------------------------------------------------------------------
// Kernel 2: tiny per-batch MLP -> g_scale
// ---------------------------------------------------------------------------
__global__ void mlp_kernel(const float* __restrict__ w1, const float* __restrict__ b1,
                           const float* __restrict__ w2, const float* __restrict__ b2) {
    __shared__ float avg[CC], mx[CC], h[2 * HID];
    const int b = blockIdx.x, c = threadIdx.x;
    avg[c] = g_avg[b * CC + c];
    mx[c]  = g_maxv[b * CC + c];
    __syncthreads();
    if (c < 2 * HID) {
        int j = c & (HID - 1);
        const float* pool = (c < HID) ? avg : mx;
        float s = b1[j];
#pragma unroll 8
        for (int i = 0; i < CC; i++) s += pool[i] * w1[i * HID + j];
        h[c] = fmaxf(s, 0.f);
    }
    __syncthreads();
    float s = 2.f * b2[c];
#pragma unroll
    for (int j = 0; j < HID; j++) s += (h[j] + h[HID + j]) * w2[j * CC + c];
    g_scale[b * CC + c] = 1.f / (1.f + __expf(-s));
}

// ---------------------------------------------------------------------------
// Kernel 3: y = x * scale[row]
// ---------------------------------------------------------------------------
__global__ __launch_bounds__(256) void scale_kernel(const float* __restrict__ x,
                                                    float* __restrict__ y) {
    const int row = blockIdx.x;
    const float s = g_scale[row];
    const float4* xi = (const float4*)(x + (size_t)row * HW);
    float4* yo = (float4*)(y + (size_t)row * HW);
    const int t = threadIdx.x;
#pragma unroll
    for (int i = 0; i < HW / (4 * 256); i++) {
        float4 v = xi[t + i * 256];
        v.x *= s; v.y *= s; v.z *= s; v.w *= s;
        yo[t + i * 256] = v;
    }
}

extern "C" void kernel_launch(void* const* d_in, const int* in_sizes, int n_in,
                              void* d_out, int out_size) {
    const float* x  = (const float*)d_in[0];
    const float* w1 = (const float*)d_in[1];
    const float* b1 = (const float*)d_in[2];
    const float* w2 = (const float*)d_in[3];
    const float* b2 = (const float*)d_in[4];
    float* y = (float*)d_out;

    topk_stats<<<ROWS, NT>>>(x);
    mlp_kernel<<<BB, CC>>>(w1, b1, w2, b2);
    scale_kernel<<<ROWS, 256>>>(x, y);
}

// round 11
// speedup vs baseline: 1.8289x; 1.0667x over previous
#include <cuda_runtime.h>

#define HW    16384      // H*W
#define ROWS  4096       // B*C
#define CC    128
#define BB    32
#define TOPK  1638       // round(16384 * 0.1)
#define HID   8
#define NT    256
#define NWARP 8
#define SLOT  28         // per-thread candidate slots (64 elems/thread, ~10 hits)
#define STRIDE 29        // SLOT real slots + 1 dump slot
#define NBH   1792       // histogram bins (7/thread); valid ids [0,1536]
#define BUFN  256        // threshold-bin buffer
#define T_LO  1.0f
#define FONE  0x3F800000u

__device__ float g_avg[ROWS];
__device__ float g_maxv[ROWS];
__device__ float g_scale[ROWS];

__device__ __forceinline__ unsigned f2key(float f) {
    unsigned u = __float_as_uint(f);
    return u ^ ((unsigned)((int)u >> 31) | 0x80000000u);
}
__device__ __forceinline__ float key2f(unsigned k) {
    unsigned u = k ^ (((int)k < 0) ? 0x80000000u : 0xFFFFFFFFu);
    return __uint_as_float(u);
}
__device__ __forceinline__ int vbin(float v) {
    return min((int)((__float_as_uint(v) - FONE) >> 14), 1536);
}

// Suffix-count select: bin b with s(b) >= rem > s(b+1), s(b)=sum_{j>=b} h[j].
template <int BPT>
__device__ __forceinline__ void suffix_select(const int* h, int rem,
                                              int* swarp, unsigned* sdigit,
                                              int* srem) {
    const int tid = threadIdx.x, lane = tid & 31, w = tid >> 5;
    const int base = tid * BPT;
    int loc[BPT];
    int tsum = 0;
#pragma unroll
    for (int i = 0; i < BPT; i++) { loc[i] = h[base + i]; tsum += loc[i]; }
    int inc = tsum;                       // suffix over lanes >= lane
#pragma unroll
    for (int o = 1; o < 32; o <<= 1) {
        int v = __shfl_down_sync(0xffffffffu, inc, o);
        if (lane + o < 32) inc += v;
    }
    if (lane == 0) swarp[w] = inc;
    __syncthreads();
    if (tid < 32) {
        int v = (lane < NWARP) ? swarp[lane] : 0;
        int s = v;
#pragma unroll
        for (int o = 1; o < 32; o <<= 1) {
            int t = __shfl_down_sync(0xffffffffu, s, o);
            if (lane + o < 32) s += t;
        }
        if (lane < NWARP) swarp[lane] = s - v;   // exclusive suffix above this warp
    }
    __syncthreads();
    int s_next = (inc - tsum) + swarp[w];
#pragma unroll
    for (int i = BPT - 1; i >= 0; i--) {
        int s = loc[i] + s_next;
        if (s >= rem && s_next < rem) { *sdigit = (unsigned)(base + i); *srem = rem - s_next; }
        s_next = s;
    }
    __syncthreads();
}

// ---------------------------------------------------------------------------
// Pass 1: per-(b,c) top-k mean + max.
// Sweep: branch-free dump-slot compaction (no atomics, no predication bodies).
// Post-pass over ~10 candidates/thread: max + histogram.
// Then suffix-select + 14-bit in-bin binary search (warp 0).
// ---------------------------------------------------------------------------
__global__ __launch_bounds__(NT, 6) void topk_stats(const float* __restrict__ x) {
    __shared__ float    cand[NT * STRIDE];   // 29.7 KB per-thread segments (+dump)
    __shared__ int      hist[NBH];           // 7 KB
    __shared__ unsigned buf[BUFN];           // 1 KB threshold-bin members (low 14 bits)
    __shared__ int      swarp[NWARP];
    __shared__ unsigned sdigit, suT;
    __shared__ int      srem, sfall, snb;
    __shared__ float    fred[NWARP];
    __shared__ int      ired[NWARP];

    const int tid = threadIdx.x, lane = tid & 31, w = tid >> 5;
    const int row = blockIdx.x;
    const float4* xin = (const float4*)(x + (size_t)row * HW);
    float* seg = cand + tid * STRIDE;

    // zero histogram (filled by post-pass)
#pragma unroll
    for (int i = 0; i < NBH / NT; i++) hist[tid + i * NT] = 0;
    if (tid == 0) snb = 0;
    __syncthreads();

    // ---- sweep: branch-free compaction with dump slot ----
    int cnt = 0;
#pragma unroll 8
    for (int i = 0; i < HW / (4 * NT); i++) {
        float4 v = xin[tid + i * NT];
        int h0 = v.x > T_LO, h1 = v.y > T_LO, h2 = v.z > T_LO, h3 = v.w > T_LO;
        int p0 = cnt, p1 = p0 + h0, p2 = p1 + h1, p3 = p2 + h2;
        seg[h0 ? min(p0, SLOT) : SLOT] = v.x;
        seg[h1 ? min(p1, SLOT) : SLOT] = v.y;
        seg[h2 ? min(p2, SLOT) : SLOT] = v.z;
        seg[h3 ? min(p3, SLOT) : SLOT] = v.w;
        cnt = p3 + h3;
    }

    // ---- post-pass over real candidates: max + histogram ----
    const int mc = min(cnt, SLOT);
    float lmax = -3.402823466e38f;
    for (int i = 0; i < mc; i++) {
        float v = seg[i];
        lmax = fmaxf(lmax, v);
        atomicAdd(&hist[vbin(v)], 1);
    }

    int of = (cnt > SLOT) ? 1 : 0;
    int tot = cnt;
#pragma unroll
    for (int o = 16; o; o >>= 1) {
        lmax = fmaxf(lmax, __shfl_down_sync(0xffffffffu, lmax, o));
        tot += __shfl_down_sync(0xffffffffu, tot, o);
        of  |= __shfl_down_sync(0xffffffffu, of, o);
    }
    if (lane == 0) { fred[w] = lmax; ired[w] = tot; swarp[w] = of; }
    __syncthreads();
    if (tid == 0) {
        float m = fred[0]; int t = 0, o = 0;
        for (int i = 0; i < NWARP; i++) { m = fmaxf(m, fred[i]); t += ired[i]; o |= swarp[i]; }
        sfall = (o || t < TOPK);
        if (!sfall) g_maxv[row] = m;     // fast path: max is among candidates
    }
    __syncthreads();

    if (!sfall) {
        suffix_select<NBH / NT>(hist, TOPK, swarp, &sdigit, &srem);
        const unsigned d0 = sdigit; const int rem1 = srem;

        if (d0 >= 1536) { if (tid == 0) sfall = 1; }
        else {
            // collect threshold-bin members (low 14 bits) into buf
            for (int i = 0; i < mc; i++) {
                unsigned u = __float_as_uint(seg[i]);
                if ((u - FONE) >> 14 == d0) {
                    int p = atomicAdd(&snb, 1);
                    if (p < BUFN) buf[p] = u & 0x3FFFu;
                }
            }
            __syncthreads();
            if (snb > BUFN) { if (tid == 0) sfall = 1; }
            else if (w == 0) {
                // warp 0: bitwise binary search over low 14 bits for rem1-th largest
                const int nb = snb;
                const int nj = (nb + 31) >> 5;
                unsigned my[BUFN / 32];
                for (int j = 0; j < nj; j++)
                    my[j] = (lane + 32 * j < nb) ? buf[lane + 32 * j] : 0u;
                unsigned T = 0u;
#pragma unroll
                for (int bit = 13; bit >= 0; --bit) {
                    unsigned cT = T | (1u << bit);
                    int c = 0;
                    for (int j = 0; j < nj; j++)
                        c += __popc(__ballot_sync(0xffffffffu, my[j] >= cT));
                    if (c >= rem1) T = cT;
                }
                if (lane == 0) suT = FONE | (d0 << 14) | T;
            }
        }
        __syncthreads();

        if (!sfall) {
            // ---- final: sum/count of candidates strictly above threshold ----
            const float Tval = __uint_as_float(suT);
            float ls = 0.f; int lc = 0;
            for (int i = 0; i < mc; i++) {
                float v = seg[i];
                if (v > Tval) { ls += v; lc++; }
            }
#pragma unroll
            for (int o = 16; o; o >>= 1) {
                ls += __shfl_down_sync(0xffffffffu, ls, o);
                lc += __shfl_down_sync(0xffffffffu, lc, o);
            }
            if (lane == 0) { fred[w] = ls; ired[w] = lc; }
            __syncthreads();
            if (tid == 0) {
                float s = 0.f; int c = 0;
                for (int i = 0; i < NWARP; i++) { s += fred[i]; c += ired[i]; }
                g_avg[row] = (s + Tval * (float)(TOPK - c)) / (float)TOPK;
            }
            return;
        }
    }

    // ---- exact fallback: bitwise binary search over full 32-bit keys ----
    {
        unsigned T = 0u;
        for (int bit = 31; bit >= 0; --bit) {
            const unsigned cT = T | (1u << bit);
            int c = 0;
#pragma unroll 4
            for (int i = 0; i < HW / (4 * NT); i++) {
                float4 v = xin[tid + i * NT];
                c += (f2key(v.x) >= cT) + (f2key(v.y) >= cT)
                   + (f2key(v.z) >= cT) + (f2key(v.w) >= cT);
            }
#pragma unroll
            for (int o = 16; o; o >>= 1) c += __shfl_down_sync(0xffffffffu, c, o);
            if (lane == 0) ired[w] = c;
            __syncthreads();
            if (tid == 0) {
                int s = 0;
                for (int i = 0; i < NWARP; i++) s += ired[i];
                srem = s;
            }
            __syncthreads();
            if (srem >= TOPK) T = cT;
            __syncthreads();
        }
        float ls = 0.f; int lc = 0;
        float lmax2 = -3.402823466e38f;
#pragma unroll 4
        for (int i = 0; i < HW / (4 * NT); i++) {
            float4 v = xin[tid + i * NT];
            lmax2 = fmaxf(lmax2, fmaxf(fmaxf(v.x, v.y), fmaxf(v.z, v.w)));
            float vv[4] = {v.x, v.y, v.z, v.w};
#pragma unroll
            for (int j = 0; j < 4; j++) {
                unsigned kk = f2key(vv[j]);
                if (kk > T) { ls += vv[j]; lc++; }
            }
        }
#pragma unroll
        for (int o = 16; o; o >>= 1) {
            ls += __shfl_down_sync(0xffffffffu, ls, o);
            lc += __shfl_down_sync(0xffffffffu, lc, o);
            lmax2 = fmaxf(lmax2, __shfl_down_sync(0xffffffffu, lmax2, o));
        }
        if (lane == 0) { fred[w] = ls; ired[w] = lc; cand[w] = lmax2; }
        __syncthreads();
        if (tid == 0) {
            float s = 0.f; int c = 0; float m = cand[0];
            for (int i = 0; i < NWARP; i++) { s += fred[i]; c += ired[i]; m = fmaxf(m, cand[i]); }
            g_avg[row] = (s + key2f(T) * (float)(TOPK - c)) / (float)TOPK;
            g_maxv[row] = m;
        }
    }
}

// ---------------------------------------------------------------------------
// Kernel 2: tiny per-batch MLP -> g_scale
// ---------------------------------------------------------------------------
__global__ void mlp_kernel(const float* __restrict__ w1, const float* __restrict__ b1,
                           const float* __restrict__ w2, const float* __restrict__ b2) {
    __shared__ float avg[CC], mx[CC], h[2 * HID];
    const int b = blockIdx.x, c = threadIdx.x;
    avg[c] = g_avg[b * CC + c];
    mx[c]  = g_maxv[b * CC + c];
    __syncthreads();
    if (c < 2 * HID) {
        int j = c & (HID - 1);
        const float* pool = (c < HID) ? avg : mx;
        float s = b1[j];
#pragma unroll 8
        for (int i = 0; i < CC; i++) s += pool[i] * w1[i * HID + j];
        h[c] = fmaxf(s, 0.f);
    }
    __syncthreads();
    float s = 2.f * b2[c];
#pragma unroll
    for (int j = 0; j < HID; j++) s += (h[j] + h[HID + j]) * w2[j * CC + c];
    g_scale[b * CC + c] = 1.f / (1.f + __expf(-s));
}

// ---------------------------------------------------------------------------
// Kernel 3: y = x * scale[row]
// ---------------------------------------------------------------------------
__global__ __launch_bounds__(256) void scale_kernel(const float* __restrict__ x,
                                                    float* __restrict__ y) {
    const int row = blockIdx.x;
    const float s = g_scale[row];
    const float4* xi = (const float4*)(x + (size_t)row * HW);
    float4* yo = (float4*)(y + (size_t)row * HW);
    const int t = threadIdx.x;
#pragma unroll
    for (int i = 0; i < HW / (4 * 256); i++) {
        float4 v = xi[t + i * 256];
        v.x *= s; v.y *= s; v.z *= s; v.w *= s;
        yo[t + i * 256] = v;
    }
}

extern "C" void kernel_launch(void* const* d_in, const int* in_sizes, int n_in,
                              void* d_out, int out_size) {
    const float* x  = (const float*)d_in[0];
    const float* w1 = (const float*)d_in[1];
    const float* b1 = (const float*)d_in[2];
    const float* w2 = (const float*)d_in[3];
    const float* b2 = (const float*)d_in[4];
    float* y = (float*)d_out;

    topk_stats<<<ROWS, NT>>>(x);
    mlp_kernel<<<BB, CC>>>(w1, b1, w2, b2);
    scale_kernel<<<ROWS, 256>>>(x, y);
}